// round 7
// baseline (speedup 1.0000x reference)
#include <cuda_runtime.h>
#include <cstdint>

#define V      50000
#define BATCH  64
#define MLEN   2048
#define DIM    128
#define NPART  250
#define NSTEPS 3125   // V/16 exactly
#define NTOK   (MLEN * BATCH * 4)   // 524288 tokens

// ---------------- scratch (device globals; no allocs allowed) ----------------
__device__ float g_w[3 * V * BATCH];          // wT[hop][v][b]  (38.4 MB)
__device__ float g_proj[V * BATCH];           // proj[v][b]     (12.8 MB)
__device__ float g_prob[BATCH * MLEN];        // scores -> probs [b][m]
__device__ float g_u[BATCH * DIM];            // running u [b][d]
__device__ float g_part[NPART * BATCH * DIM]; // split-K partials (8.2 MB)
__device__ int   g_tok[NTOK];                 // normalized int32 tokens (2 MB)
__device__ int   g_is32;                      // dtype probe result

// ---------------- f32x2 helpers (FFMA2 — only reachable via PTX) -------------
__device__ __forceinline__ unsigned long long pk2(float lo, float hi) {
    unsigned long long r;
    asm("mov.b64 %0, {%1, %2};" : "=l"(r) : "f"(lo), "f"(hi));
    return r;
}
__device__ __forceinline__ void fma2(unsigned long long& d,
                                     unsigned long long a,
                                     unsigned long long b) {
    asm("fma.rn.f32x2 %0, %1, %2, %0;" : "+l"(d) : "l"(a), "l"(b));
}
__device__ __forceinline__ float2 upk(unsigned long long v) {
    float2 f;
    asm("mov.b64 {%0, %1}, %2;" : "=f"(f.x), "=f"(f.y) : "l"(v));
    return f;
}

// ---------------- K0: zero accumulators + probe flag (every replay) ----------
__global__ void k_zero() {
    const float4 z = make_float4(0.f, 0.f, 0.f, 0.f);
    int t = blockIdx.x * blockDim.x + threadIdx.x;
    int stride = gridDim.x * blockDim.x;
    float4* w4 = reinterpret_cast<float4*>(g_w);
    const int NW4 = 3 * V * BATCH / 4;  // 2,400,000
    for (int i = t; i < NW4; i += stride) w4[i] = z;
    if (t < (BATCH * DIM / 4)) reinterpret_cast<float4*>(g_u)[t] = z;
    if (t == 0) g_is32 = 0;
}

// ---------------- K0b: dtype probe -------------------------------------------
// Scan odd 32-bit words within the first NTOK words (safe for both dtypes).
// int64 little-endian: those are high halves of the first NTOK/2 tokens -> all 0.
// int32: those are real tokens (~random in [0,50000)) -> almost all nonzero.
__global__ void k_detect(const unsigned* __restrict__ s) {
    int t = blockIdx.x * blockDim.x + threadIdx.x;
    int stride = gridDim.x * blockDim.x;
    int found = 0;
    for (int w = 2 * t + 1; w < NTOK; w += 2 * stride)
        found |= (s[w] != 0u);
    if (found) g_is32 = 1;
}

// ---------------- K0c: normalize story into g_tok ----------------------------
__global__ void k_convert(const int* __restrict__ s) {
    int t = blockIdx.x * blockDim.x + threadIdx.x;
    if (t >= NTOK) return;
    g_tok[t] = g_is32 ? s[t] : s[2 * t];   // int64: low word at 2*t (LE)
}

// ---------------- K1: scatter counts for hop0 (uniform softmax) --------------
__global__ void k_scatter_count() {
    int t = blockIdx.x * blockDim.x + threadIdx.x;   // 131072 = (m,b)
    if (t >= MLEN * BATCH) return;
    int b = t & (BATCH - 1);
    int4 s4 = *reinterpret_cast<const int4*>(g_tok + t * 4);
    if (s4.x) atomicAdd(&g_w[s4.x * BATCH + b], 1.0f);
    if (s4.y) atomicAdd(&g_w[s4.y * BATCH + b], 1.0f);
    if (s4.z) atomicAdd(&g_w[s4.z * BATCH + b], 1.0f);
    if (s4.w) atomicAdd(&g_w[s4.w * BATCH + b], 1.0f);
}

// ---------------- K2: proj[v][b] = C[h][v] . u[b]  (V x 64, K=128) -----------
#define AS_W 132
#define BS_W 68
__global__ __launch_bounds__(256) void k_proj(const float* __restrict__ Ct) {
    __shared__ __align__(16) float As[16 * AS_W];
    __shared__ __align__(16) float Bs[16 * BS_W];
    int t = threadIdx.x;
    int v0 = blockIdx.x * 128;
    int vg = t & 15;         // 16 v-groups of 8 rows
    int bg = t >> 4;         // 16 b-groups of 4 cols
    unsigned long long acc[4][4];
#pragma unroll
    for (int i = 0; i < 4; i++)
#pragma unroll
        for (int j = 0; j < 4; j++) acc[i][j] = 0ULL;

#pragma unroll 1
    for (int kk = 0; kk < 8; kk++) {
        int kb = kk * 16;
#pragma unroll
        for (int i = 0; i < 8; i++) {          // stage C tile (k-fast, coalesced)
            int e = t + i * 256;
            int k = e & 15, v = e >> 4;
            int gv = v0 + v;
            float val = (gv < V) ? Ct[(size_t)gv * DIM + kb + k] : 0.f;
            As[k * AS_W + v] = val;
        }
#pragma unroll
        for (int i = 0; i < 4; i++) {          // stage u tile
            int e = t + i * 256;
            int k = e & 15, b = e >> 4;
            Bs[k * BS_W + b] = g_u[b * DIM + kb + k];
        }
        __syncthreads();
#pragma unroll
        for (int k = 0; k < 16; k++) {
            const ulonglong2* ap =
                reinterpret_cast<const ulonglong2*>(&As[k * AS_W + vg * 8]);
            ulonglong2 a01 = ap[0], a23 = ap[1];  // (v0,v1)(v2,v3)(v4,v5)(v6,v7)
            float4 b4 = *reinterpret_cast<const float4*>(&Bs[k * BS_W + bg * 4]);
            unsigned long long bd0 = pk2(b4.x, b4.x), bd1 = pk2(b4.y, b4.y);
            unsigned long long bd2 = pk2(b4.z, b4.z), bd3 = pk2(b4.w, b4.w);
            fma2(acc[0][0], a01.x, bd0); fma2(acc[0][1], a01.x, bd1);
            fma2(acc[0][2], a01.x, bd2); fma2(acc[0][3], a01.x, bd3);
            fma2(acc[1][0], a01.y, bd0); fma2(acc[1][1], a01.y, bd1);
            fma2(acc[1][2], a01.y, bd2); fma2(acc[1][3], a01.y, bd3);
            fma2(acc[2][0], a23.x, bd0); fma2(acc[2][1], a23.x, bd1);
            fma2(acc[2][2], a23.x, bd2); fma2(acc[2][3], a23.x, bd3);
            fma2(acc[3][0], a23.y, bd0); fma2(acc[3][1], a23.y, bd1);
            fma2(acc[3][2], a23.y, bd2); fma2(acc[3][3], a23.y, bd3);
        }
        __syncthreads();
    }
#pragma unroll
    for (int ip = 0; ip < 4; ip++) {
        float2 r0 = upk(acc[ip][0]), r1 = upk(acc[ip][1]);
        float2 r2 = upk(acc[ip][2]), r3 = upk(acc[ip][3]);
        int ve = v0 + vg * 8 + ip * 2;
        if (ve < V)
            *reinterpret_cast<float4*>(&g_proj[(size_t)ve * BATCH + bg * 4]) =
                make_float4(r0.x, r1.x, r2.x, r3.x);
        if (ve + 1 < V)
            *reinterpret_cast<float4*>(&g_proj[(size_t)(ve + 1) * BATCH + bg * 4]) =
                make_float4(r0.y, r1.y, r2.y, r3.y);
    }
}

// ---------------- K3: scores s[b][m] = sum_t (tok!=0) proj[tok][b] -----------
__global__ void k_scores() {
    int t = blockIdx.x * blockDim.x + threadIdx.x;   // t = b*2048 + m
    if (t >= BATCH * MLEN) return;
    int b = t >> 11, m = t & (MLEN - 1);
    int4 s4 = *reinterpret_cast<const int4*>(g_tok + (m * BATCH + b) * 4);
    float sum = 0.f;
    if (s4.x) sum += __ldg(&g_proj[(size_t)s4.x * BATCH + b]);
    if (s4.y) sum += __ldg(&g_proj[(size_t)s4.y * BATCH + b]);
    if (s4.z) sum += __ldg(&g_proj[(size_t)s4.z * BATCH + b]);
    if (s4.w) sum += __ldg(&g_proj[(size_t)s4.w * BATCH + b]);
    g_prob[t] = sum;
}

// ---------------- K4: softmax over M per batch -------------------------------
__global__ void k_softmax() {
    __shared__ __align__(16) float sc[MLEN];
    __shared__ float red[256];
    int b = blockIdx.x, t = threadIdx.x;
    float lmax = -1e30f;
#pragma unroll
    for (int i = 0; i < 8; i++) {
        float v = g_prob[b * MLEN + t + i * 256];
        sc[t + i * 256] = v;
        lmax = fmaxf(lmax, v);
    }
    red[t] = lmax; __syncthreads();
    for (int s = 128; s > 0; s >>= 1) {
        if (t < s) red[t] = fmaxf(red[t], red[t + s]);
        __syncthreads();
    }
    float mx = red[0]; __syncthreads();
    float lsum = 0.f;
#pragma unroll
    for (int i = 0; i < 8; i++) {
        float e = expf(sc[t + i * 256] - mx);
        sc[t + i * 256] = e;
        lsum += e;
    }
    red[t] = lsum; __syncthreads();
    for (int s = 128; s > 0; s >>= 1) {
        if (t < s) red[t] += red[t + s];
        __syncthreads();
    }
    float inv = 1.0f / red[0];
#pragma unroll
    for (int i = 0; i < 8; i++)
        g_prob[b * MLEN + t + i * 256] = sc[t + i * 256] * inv;
}

// ---------------- K5: scatter probs into wT[hop] -----------------------------
__global__ void k_scatter_prob(int hop) {
    int t = blockIdx.x * blockDim.x + threadIdx.x;   // t = m*64 + b
    if (t >= MLEN * BATCH) return;
    int b = t & (BATCH - 1), m = t >> 6;
    float p = g_prob[b * MLEN + m];
    float* w = g_w + (size_t)hop * V * BATCH;
    int4 s4 = *reinterpret_cast<const int4*>(g_tok + t * 4);
    if (s4.x) atomicAdd(&w[s4.x * BATCH + b], p);
    if (s4.y) atomicAdd(&w[s4.y * BATCH + b], p);
    if (s4.z) atomicAdd(&w[s4.z * BATCH + b], p);
    if (s4.w) atomicAdd(&w[s4.w * BATCH + b], p);
}

// ---------------- K6: o[b][d] partials = w @ C[tab]  (split-K) ---------------
__global__ __launch_bounds__(256) void k_gemm2(const float* __restrict__ Ct,
                                               int hop) {
    __shared__ __align__(16) float Cs[16 * 128];
    __shared__ __align__(16) float Ws[16 * 64];
    const float* wT = g_w + (size_t)hop * V * BATCH;
    int t = threadIdx.x;
    int dg = t & 31;     // 32 d-groups of 4
    int bgp = t >> 5;    // 8 b-groups of 8
    int s0 = (int)((long long)blockIdx.x * NSTEPS / NPART);
    int s1 = (int)((long long)(blockIdx.x + 1) * NSTEPS / NPART);
    unsigned long long acc[4][4];   // [b-pair][d]
#pragma unroll
    for (int i = 0; i < 4; i++)
#pragma unroll
        for (int j = 0; j < 4; j++) acc[i][j] = 0ULL;

    for (int s = s0; s < s1; s++) {
        int vb = s * 16;
#pragma unroll
        for (int i = 0; i < 8; i++) {
            int e = t + i * 256;
            Cs[e] = Ct[(size_t)vb * 128 + e];
        }
#pragma unroll
        for (int i = 0; i < 4; i++) {
            int e = t + i * 256;
            Ws[e] = wT[(size_t)vb * 64 + e];
        }
        __syncthreads();
#pragma unroll
        for (int vv = 0; vv < 16; vv++) {
            const ulonglong2* wp =
                reinterpret_cast<const ulonglong2*>(&Ws[vv * 64 + bgp * 8]);
            ulonglong2 w01 = wp[0], w23 = wp[1];  // (b0,b1)(b2,b3)(b4,b5)(b6,b7)
            float4 c4 = *reinterpret_cast<const float4*>(&Cs[vv * 128 + dg * 4]);
            unsigned long long cd0 = pk2(c4.x, c4.x), cd1 = pk2(c4.y, c4.y);
            unsigned long long cd2 = pk2(c4.z, c4.z), cd3 = pk2(c4.w, c4.w);
            fma2(acc[0][0], w01.x, cd0); fma2(acc[0][1], w01.x, cd1);
            fma2(acc[0][2], w01.x, cd2); fma2(acc[0][3], w01.x, cd3);
            fma2(acc[1][0], w01.y, cd0); fma2(acc[1][1], w01.y, cd1);
            fma2(acc[1][2], w01.y, cd2); fma2(acc[1][3], w01.y, cd3);
            fma2(acc[2][0], w23.x, cd0); fma2(acc[2][1], w23.x, cd1);
            fma2(acc[2][2], w23.x, cd2); fma2(acc[2][3], w23.x, cd3);
            fma2(acc[3][0], w23.y, cd0); fma2(acc[3][1], w23.y, cd1);
            fma2(acc[3][2], w23.y, cd2); fma2(acc[3][3], w23.y, cd3);
        }
        __syncthreads();
    }
    float* pp = g_part + (size_t)blockIdx.x * (BATCH * DIM);
#pragma unroll
    for (int bp = 0; bp < 4; bp++) {
        float2 e0 = upk(acc[bp][0]), e1 = upk(acc[bp][1]);
        float2 e2 = upk(acc[bp][2]), e3 = upk(acc[bp][3]);
        int be = bgp * 8 + bp * 2;
        *reinterpret_cast<float4*>(&pp[be * DIM + dg * 4]) =
            make_float4(e0.x, e1.x, e2.x, e3.x);
        *reinterpret_cast<float4*>(&pp[(be + 1) * DIM + dg * 4]) =
            make_float4(e0.y, e1.y, e2.y, e3.y);
    }
}

// ---------------- K7: reduce partials, update u, optionally emit out ---------
__global__ void k_reduce(float scale, float* out) {
    int i = blockIdx.x * blockDim.x + threadIdx.x;   // 8192
    float s = 0.f;
#pragma unroll 10
    for (int k = 0; k < NPART; k++) s += g_part[(size_t)k * (BATCH * DIM) + i];
    float un = g_u[i] + scale * s;
    g_u[i] = un;
    if (out) out[i] = un;
}

// -----------------------------------------------------------------------------
extern "C" void kernel_launch(void* const* d_in, const int* in_sizes, int n_in,
                              void* d_out, int out_size) {
    const void* story;
    const float* C;
    if (in_sizes[0] == NTOK) {
        story = d_in[0];
        C = (const float*)d_in[1];
    } else {
        story = d_in[1];
        C = (const float*)d_in[0];
    }
    float* out = (float*)d_out;
    const float* C1 = C + (size_t)1 * V * DIM;
    const float* C2 = C + (size_t)2 * V * DIM;
    const float* C3 = C + (size_t)3 * V * DIM;

    const int PROJ_BLKS = (V + 127) / 128;       // 391
    const int BM_BLKS = (MLEN * BATCH) / 256;    // 512
    const int TOK_BLKS = NTOK / 256;             // 2048

    k_zero<<<2048, 256>>>();
    k_detect<<<256, 256>>>((const unsigned*)story);
    k_convert<<<TOK_BLKS, 256>>>((const int*)story);

    // hop 0: uniform softmax -> u1 = (1/M) * counts @ C1
    k_scatter_count<<<BM_BLKS, 256>>>();
    k_gemm2<<<NPART, 256>>>(C1, 0);
    k_reduce<<<32, 256>>>(1.0f / (float)MLEN, nullptr);

    // hop 1: scores with C1 & u1, values from C2
    k_proj<<<PROJ_BLKS, 256>>>(C1);
    k_scores<<<BM_BLKS, 256>>>();
    k_softmax<<<BATCH, 256>>>();
    k_scatter_prob<<<BM_BLKS, 256>>>(1);
    k_gemm2<<<NPART, 256>>>(C2, 1);
    k_reduce<<<32, 256>>>(1.0f, nullptr);

    // hop 2: scores with C2 & u2, values from C3
    k_proj<<<PROJ_BLKS, 256>>>(C2);
    k_scores<<<BM_BLKS, 256>>>();
    k_softmax<<<BATCH, 256>>>();
    k_scatter_prob<<<BM_BLKS, 256>>>(2);
    k_gemm2<<<NPART, 256>>>(C3, 2);
    k_reduce<<<32, 256>>>(1.0f, out);
}